// round 15
// baseline (speedup 1.0000x reference)
#include <cuda_runtime.h>
#include <math.h>
#include <stdint.h>

// ---------------------------------------------------------------------------
// Problem constants
// ---------------------------------------------------------------------------
#define DD    1024
#define NTOK  257
#define BATCH 32
#define HEADS 16
#define HDIM  64
#define RR    16
#define NA    129        // even tokens (a side)
#define NB    128        // odd tokens  (b side)
#define NUNM  113        // NA - RR
#define NOUT  241        // NUNM + NB
#define MROWS (BATCH*NTOK)   // 8224
#define MOUT  (BATCH*NOUT)   // 7712

// ---------------------------------------------------------------------------
// Scratch (device globals -- no allocation allowed)
// ---------------------------------------------------------------------------
__device__ float g_h   [MROWS*DD];          // LN1 output (fp32 exact, metric path)
__device__ float g_ht  [MROWS*DD];          // LN1 output (tf32-rounded, GEMM A)
__device__ float g_qkv [MROWS*3*DD];        // qkv projections
__device__ float g_o   [MROWS*DD];          // attention output (tf32-rounded)
__device__ float g_xf  [MROWS*DD];          // x after attention residual (exact)
__device__ float g_m   [MROWS*HDIM];        // normalized metric (fp32 path)
__device__ float g_wavgT[DD*HDIM];          // head-averaged Wk, transposed
__device__ float g_bavg [HDIM];
__device__ float g_nmax[BATCH*NA];
__device__ int   g_nidx[BATCH*NA];
__device__ int   g_unm [BATCH][NUNM];
__device__ int   g_src [BATCH][RR];
__device__ int   g_dst [BATCH][RR];
__device__ int   g_dcnt[BATCH][NB];
__device__ float g_xm  [MOUT*DD];           // merged x (exact)
__device__ float g_h2  [MOUT*DD];           // LN2 output (tf32-rounded)
__device__ float g_t4  [MOUT*4*DD];         // fc+gelu output (tf32-rounded)
// tf32-rounded weight copies
__device__ float g_w_in  [3*DD*DD];
__device__ float g_w_out [DD*DD];
__device__ float g_w_fc  [4*DD*DD];
__device__ float g_w_proj[4*DD*DD];

// ---------------------------------------------------------------------------
// Helpers
// ---------------------------------------------------------------------------
__device__ __forceinline__ float gelu_exact(float x) {
    return 0.5f * x * (1.0f + erff(x * 0.70710678118654752440f));
}

__device__ __forceinline__ unsigned f2tf(float x) {
    unsigned u;
    asm("cvt.rna.tf32.f32 %0, %1;" : "=r"(u) : "f"(x));
    return u;
}
__device__ __forceinline__ float rtf(float x) {
    return __uint_as_float(f2tf(x));
}

__device__ __forceinline__ uint32_t smem_u32(const void* p) {
    uint32_t a;
    asm("{ .reg .u64 t; cvta.to.shared.u64 t, %1; cvt.u32.u64 %0, t; }"
        : "=r"(a) : "l"(p));
    return a;
}

__device__ __forceinline__ void cp16(uint32_t s, const void* g) {
    asm volatile("cp.async.cg.shared.global [%0], [%1], 16;"
                 :: "r"(s), "l"(g) : "memory");
}
#define CP_COMMIT() asm volatile("cp.async.commit_group;" ::: "memory")
#define CP_WAIT1()  asm volatile("cp.async.wait_group 1;" ::: "memory")
#define CP_WAIT0()  asm volatile("cp.async.wait_group 0;" ::: "memory")

__device__ __forceinline__ void mma_tf32(float c[4], const unsigned a[4],
                                         const unsigned b[2]) {
    asm volatile(
        "mma.sync.aligned.m16n8k8.row.col.f32.tf32.tf32.f32 "
        "{%0,%1,%2,%3}, {%4,%5,%6,%7}, {%8,%9}, {%0,%1,%2,%3};\n"
        : "+f"(c[0]), "+f"(c[1]), "+f"(c[2]), "+f"(c[3])
        : "r"(a[0]), "r"(a[1]), "r"(a[2]), "r"(a[3]),
          "r"(b[0]), "r"(b[1]));
}

// ---------------------------------------------------------------------------
// Round weights to tf32 (rna) into scratch copies
// ---------------------------------------------------------------------------
__global__ __launch_bounds__(256)
void roundw_kernel(const float4* __restrict__ s, float4* __restrict__ d, int n4)
{
    int i = blockIdx.x * blockDim.x + threadIdx.x;
    if (i < n4) {
        float4 v = s[i];
        v.x = rtf(v.x); v.y = rtf(v.y); v.z = rtf(v.z); v.w = rtf(v.w);
        d[i] = v;
    }
}

// ---------------------------------------------------------------------------
// LayerNorm: one block per row of 1024, 256 threads (4 floats/thread).
// y: exact output (nullable). yt: tf32-rounded output (nullable).
// ---------------------------------------------------------------------------
__global__ __launch_bounds__(256)
void ln_kernel(const float* __restrict__ x, const float* __restrict__ w,
               const float* __restrict__ b, float* __restrict__ y,
               float* __restrict__ yt)
{
    int r = blockIdx.x;
    const float4* xr = (const float4*)(x + (size_t)r * DD);
    float4 v = xr[threadIdx.x];
    float s  = v.x + v.y + v.z + v.w;
    float s2 = v.x*v.x + v.y*v.y + v.z*v.z + v.w*v.w;
    #pragma unroll
    for (int off = 16; off; off >>= 1) {
        s  += __shfl_xor_sync(0xffffffffu, s,  off);
        s2 += __shfl_xor_sync(0xffffffffu, s2, off);
    }
    __shared__ float ws[8], ws2[8];
    int wid = threadIdx.x >> 5, lid = threadIdx.x & 31;
    if (lid == 0) { ws[wid] = s; ws2[wid] = s2; }
    __syncthreads();
    __shared__ float smu, srstd;
    if (threadIdx.x == 0) {
        float S = 0, S2 = 0;
        #pragma unroll
        for (int i = 0; i < 8; i++) { S += ws[i]; S2 += ws2[i]; }
        float mu  = S * (1.0f / DD);
        float var = S2 * (1.0f / DD) - mu * mu;
        smu = mu; srstd = rsqrtf(var + 1e-5f);
    }
    __syncthreads();
    float mu = smu, rstd = srstd;
    float4 wv = ((const float4*)w)[threadIdx.x];
    float4 bv = ((const float4*)b)[threadIdx.x];
    float4 o;
    o.x = (v.x - mu) * rstd * wv.x + bv.x;
    o.y = (v.y - mu) * rstd * wv.y + bv.y;
    o.z = (v.z - mu) * rstd * wv.z + bv.z;
    o.w = (v.w - mu) * rstd * wv.w + bv.w;
    if (y)
        ((float4*)(y + (size_t)r * DD))[threadIdx.x] = o;
    if (yt) {
        float4 t;
        t.x = rtf(o.x); t.y = rtf(o.y); t.z = rtf(o.z); t.w = rtf(o.w);
        ((float4*)(yt + (size_t)r * DD))[threadIdx.x] = t;
    }
}

// ---------------------------------------------------------------------------
// TF32 tensor-core GEMM (NT): C[m,n] = sum_k A[m,k]*W[n,k] + bias[n] (+epi)
// A and W must be tf32-pre-rounded. BM=BN=128, BK=32, 256 threads,
// warps 2x4 (warp tile 64x32). 3-stage cp.async ring => ONE barrier per
// chunk (issue(c+2) writes the buffer consumed at c-1, protected by the
// top-of-chunk barrier). 2 CTAs/SM (2 x 110.6KB smem = 221KB <= 228KB).
// EPI 0: bias. EPI 1: +Cadd residual. EPI 2: gelu(acc+bias), tf32-rounded out.
// Requires N % 128 == 0, K % 64 == 0; M guarded.
// ---------------------------------------------------------------------------
#define SAS 36
#define BUFF 4608                 // floats per matrix per buffer (128*36)
#define BUFSTR 9216               // floats per buffer (A+B)
#define NSTAGE 3
#define GEMM_SMEM (NSTAGE*BUFSTR*4)   // 110592 bytes

template<int EPI>
__global__ __launch_bounds__(256, 2)
void gemm_tf32(const float* __restrict__ A, const float* __restrict__ W,
               const float* __restrict__ bias, const float* __restrict__ Cadd,
               float* __restrict__ C, int M, int N, int K)
{
    extern __shared__ float smem[];
    uint32_t sbase = smem_u32(smem);

    int tid = threadIdx.x;
    int bx = blockIdx.x, by = blockIdx.y;

    // gmem -> smem mapping: thread covers (row = rbase+32i, 16B chunk c4)
    int rbase = tid >> 3;          // 0..31
    int c4    = tid & 7;           // 0..7
    const float* Ag[4];
    const float* Wg[4];
    uint32_t sA[4], sB[4];
    #pragma unroll
    for (int i = 0; i < 4; i++) {
        int row = rbase + 32*i;
        int ar = by*128 + row; if (ar >= M) ar = M - 1;   // clamp, epi guards
        Ag[i] = A + (size_t)ar * K + c4*4;
        Wg[i] = W + (size_t)(bx*128 + row) * K + c4*4;
        sA[i] = sbase + (row*SAS + c4*4) * 4;
        sB[i] = sbase + ((BUFF + row*SAS) + c4*4) * 4;
    }

    int NC = K >> 5;

    // issue stage c into buffer c % NSTAGE
    auto issue = [&](int c) {
        uint32_t off = (uint32_t)(c % NSTAGE) * (BUFSTR*4);
        int ko = c * 32;
        #pragma unroll
        for (int i = 0; i < 4; i++) cp16(sA[i] + off, Ag[i] + ko);
        #pragma unroll
        for (int i = 0; i < 4; i++) cp16(sB[i] + off, Wg[i] + ko);
        CP_COMMIT();
    };

    issue(0);
    issue(1);

    float acc[4][4][4];
    #pragma unroll
    for (int mt = 0; mt < 4; mt++)
        #pragma unroll
        for (int nt = 0; nt < 4; nt++)
            #pragma unroll
            for (int q = 0; q < 4; q++) acc[mt][nt][q] = 0.0f;

    int w = tid >> 5, l = tid & 31;
    int wm = w >> 2, wn = w & 3;          // 2 x 4 warp grid
    int mrow = l >> 2;                    // 0..7
    int kc   = l & 3;                     // 0..3

    for (int c = 0; c < NC; c++) {
        if (c + 1 < NC) CP_WAIT1(); else CP_WAIT0();
        __syncthreads();
        // prefetch chunk c+2 into the buffer consumed at chunk c-1
        // (all reads of it completed before the barrier above)
        if (c + 2 < NC) issue(c + 2);

        const unsigned* As = (const unsigned*)smem + (c % NSTAGE)*BUFSTR;
        const unsigned* Bs = As + BUFF;

        #pragma unroll
        for (int kk = 0; kk < 4; kk++) {
            unsigned af[4][4], bf[4][2];
            #pragma unroll
            for (int mt = 0; mt < 4; mt++) {
                int base = (wm*64 + mt*16 + mrow) * SAS + kk*8 + kc;
                af[mt][0] = As[base];
                af[mt][1] = As[base + 8*SAS];
                af[mt][2] = As[base + 4];
                af[mt][3] = As[base + 8*SAS + 4];
            }
            #pragma unroll
            for (int nt = 0; nt < 4; nt++) {
                int base = (wn*32 + nt*8 + mrow) * SAS + kk*8 + kc;
                bf[nt][0] = Bs[base];
                bf[nt][1] = Bs[base + 4];
            }
            #pragma unroll
            for (int mt = 0; mt < 4; mt++)
                #pragma unroll
                for (int nt = 0; nt < 4; nt++)
                    mma_tf32(acc[mt][nt], af[mt], bf[nt]);
        }
    }

    // epilogue
    int gr0 = by*128 + wm*64;
    int gc0 = bx*128 + wn*32;
    #pragma unroll
    for (int mt = 0; mt < 4; mt++) {
        #pragma unroll
        for (int nt = 0; nt < 4; nt++) {
            int col = gc0 + nt*8 + kc*2;
            float2 bv = *(const float2*)(bias + col);
            #pragma unroll
            for (int half = 0; half < 2; half++) {
                int row = gr0 + mt*16 + mrow + half*8;
                if (row >= M) continue;
                float r0 = acc[mt][nt][half*2+0] + bv.x;
                float r1 = acc[mt][nt][half*2+1] + bv.y;
                if constexpr (EPI == 1) {
                    float2 cv = *(const float2*)(Cadd + (size_t)row*N + col);
                    r0 += cv.x; r1 += cv.y;
                }
                if constexpr (EPI == 2) {
                    r0 = rtf(gelu_exact(r0)); r1 = rtf(gelu_exact(r1));
                }
                float2 ov = {r0, r1};
                *(float2*)(C + (size_t)row*N + col) = ov;
            }
        }
    }
}

// ---------------------------------------------------------------------------
// Fused attention: one block per (b,h). K,V resident in smem (stride 65),
// per-warp softmax over 257 keys. Output tf32-rounded (feeds GEMM only).
// ---------------------------------------------------------------------------
#define KST 65
#define PRST 260
__global__ __launch_bounds__(256)
void attn_kernel(const float* __restrict__ qkv, float* __restrict__ o)
{
    extern __shared__ float sm[];
    float* Ks = sm;                       // 257*65
    float* Vs = sm + NTOK*KST;            // 257*65
    float* Pr = Vs + NTOK*KST;            // 8*260
    float* Qb = Pr + 8*PRST;              // 8*64

    int bh = blockIdx.x;
    int b = bh >> 4, hh = bh & 15;
    const float* base = qkv + (size_t)b * NTOK * (3*DD);

    for (int idx = threadIdx.x; idx < NTOK*HDIM; idx += blockDim.x) {
        int j = idx >> 6, d = idx & 63;
        Ks[j*KST + d] = base[(size_t)j*(3*DD) + DD   + hh*HDIM + d];
        Vs[j*KST + d] = base[(size_t)j*(3*DD) + 2*DD + hh*HDIM + d];
    }
    __syncthreads();

    int w = threadIdx.x >> 5, l = threadIdx.x & 31;
    float* pr = Pr + w * PRST;
    float* qb = Qb + w * HDIM;

    for (int n = w; n < NTOK; n += 8) {
        const float* qrow = base + (size_t)n*(3*DD) + hh*HDIM;
        qb[l]      = qrow[l];
        qb[l + 32] = qrow[l + 32];
        __syncwarp();
        float mx = -INFINITY;
        for (int j = l; j < NTOK; j += 32) {
            float s = 0.0f;
            #pragma unroll
            for (int d = 0; d < HDIM; d++) s += qb[d] * Ks[j*KST + d];
            s *= 0.125f;
            pr[j] = s;
            mx = fmaxf(mx, s);
        }
        #pragma unroll
        for (int off = 16; off; off >>= 1)
            mx = fmaxf(mx, __shfl_xor_sync(0xffffffffu, mx, off));
        float sum = 0.0f;
        for (int j = l; j < NTOK; j += 32) {
            float e = expf(pr[j] - mx);
            pr[j] = e;
            sum += e;
        }
        #pragma unroll
        for (int off = 16; off; off >>= 1)
            sum += __shfl_xor_sync(0xffffffffu, sum, off);
        float inv = 1.0f / sum;
        __syncwarp();
        float o0 = 0.0f, o1 = 0.0f;
        for (int j = 0; j < NTOK; j++) {
            float p = pr[j];
            o0 += p * Vs[j*KST + l];
            o1 += p * Vs[j*KST + l + 32];
        }
        float* orow = o + ((size_t)b*NTOK + n) * DD + hh*HDIM;
        orow[l]      = rtf(o0 * inv);
        orow[l + 32] = rtf(o1 * inv);
        __syncwarp();
    }
}

// ---------------------------------------------------------------------------
// Head-averaged k-weights (fp32 exact metric path)
// ---------------------------------------------------------------------------
__global__ __launch_bounds__(256)
void wavg_kernel(const float* __restrict__ Wqkv, const float* __restrict__ bqkv,
                 float* __restrict__ wavgT, float* __restrict__ bavg)
{
    int d = blockIdx.x;                   // 0..63
    for (int c = threadIdx.x; c < DD; c += 256) {
        float s = 0.0f;
        #pragma unroll
        for (int h = 0; h < HEADS; h++)
            s += Wqkv[(size_t)(DD + h*HDIM + d) * DD + c];
        wavgT[c*HDIM + d] = s * (1.0f / HEADS);
    }
    if (threadIdx.x == 0) {
        float s = 0.0f;
        #pragma unroll
        for (int h = 0; h < HEADS; h++) s += bqkv[DD + h*HDIM + d];
        bavg[d] = s * (1.0f / HEADS);
    }
}

// ---------------------------------------------------------------------------
// metric (fp32 exact), tiled: one block = 32 rows x 64 cols. wavgT is
// streamed through smem in 64-k chunks (32x less L2 traffic than the
// per-row version). h chunk stored transposed (stride 33) => conflict-free.
// Then per-row L2 normalization (8 threads/row, shfl reduce).
// ---------------------------------------------------------------------------
__global__ __launch_bounds__(256)
void metric_gemm_kernel(const float* __restrict__ h,
                        const float* __restrict__ wavgT,
                        const float* __restrict__ bavg,
                        float* __restrict__ m)
{
    __shared__ float hsm[64*33];          // [k][row], stride 33
    __shared__ float wsm[64*64];          // [k][d]
    int tid = threadIdx.x;
    int row = tid >> 3;                   // 0..31
    int cg  = tid & 7;                    // cols cg*8 .. cg*8+7
    int rbase = blockIdx.x * 32;

    float acc[8] = {0,0,0,0,0,0,0,0};

    for (int k0 = 0; k0 < DD; k0 += 64) {
        __syncthreads();
        // load h chunk transposed: thread covers row, k = cg*8..cg*8+7
        {
            const float4* s =
                (const float4*)(h + (size_t)(rbase + row)*DD + k0 + cg*8);
            float4 v0 = s[0], v1 = s[1];
            int kb = cg*8;
            hsm[(kb+0)*33 + row] = v0.x; hsm[(kb+1)*33 + row] = v0.y;
            hsm[(kb+2)*33 + row] = v0.z; hsm[(kb+3)*33 + row] = v0.w;
            hsm[(kb+4)*33 + row] = v1.x; hsm[(kb+5)*33 + row] = v1.y;
            hsm[(kb+6)*33 + row] = v1.z; hsm[(kb+7)*33 + row] = v1.w;
        }
        // load w chunk: 64 k x 64 d = 4096 floats = 4 float4 per thread
        #pragma unroll
        for (int i = 0; i < 4; i++) {
            int idx = tid + 256*i;
            int kk = idx >> 4, d4 = idx & 15;
            *(float4*)&wsm[kk*64 + d4*4] =
                *(const float4*)(wavgT + (size_t)(k0+kk)*HDIM + d4*4);
        }
        __syncthreads();

        #pragma unroll 8
        for (int k = 0; k < 64; k++) {
            float hv = hsm[k*33 + row];
            float4 w0 = *(const float4*)&wsm[k*64 + cg*8];
            float4 w1 = *(const float4*)&wsm[k*64 + cg*8 + 4];
            acc[0] += hv*w0.x; acc[1] += hv*w0.y;
            acc[2] += hv*w0.z; acc[3] += hv*w0.w;
            acc[4] += hv*w1.x; acc[5] += hv*w1.y;
            acc[6] += hv*w1.z; acc[7] += hv*w1.w;
        }
    }

    // bias
    float4 b0 = *(const float4*)(bavg + cg*8);
    float4 b1 = *(const float4*)(bavg + cg*8 + 4);
    acc[0]+=b0.x; acc[1]+=b0.y; acc[2]+=b0.z; acc[3]+=b0.w;
    acc[4]+=b1.x; acc[5]+=b1.y; acc[6]+=b1.z; acc[7]+=b1.w;

    // row L2 norm across 8 threads (8-lane shfl groups)
    float sq = 0.0f;
    #pragma unroll
    for (int j = 0; j < 8; j++) sq += acc[j]*acc[j];
    sq += __shfl_xor_sync(0xffffffffu, sq, 1);
    sq += __shfl_xor_sync(0xffffffffu, sq, 2);
    sq += __shfl_xor_sync(0xffffffffu, sq, 4);
    float rn = rsqrtf(sq);

    float* out = m + (size_t)(rbase + row)*HDIM + cg*8;
    float4 o0 = {acc[0]*rn, acc[1]*rn, acc[2]*rn, acc[3]*rn};
    float4 o1 = {acc[4]*rn, acc[5]*rn, acc[6]*rn, acc[7]*rn};
    *(float4*)out = o0;
    *(float4*)(out + 4) = o1;
}

// ---------------------------------------------------------------------------
// node scores: block (i,b) computes max_j dot(a_i, bm_j) and argmax (first
// max wins). Row i==0 forced to -inf.
// ---------------------------------------------------------------------------
__global__ __launch_bounds__(128)
void nodescore_kernel(const float* __restrict__ m,
                      float* __restrict__ nmax, int* __restrict__ nidx)
{
    int i = blockIdx.x, b = blockIdx.y;
    if (i == 0) {
        if (threadIdx.x == 0) { nmax[b*NA] = -INFINITY; nidx[b*NA] = 0; }
        return;
    }
    __shared__ float av[HDIM];
    if (threadIdx.x < HDIM)
        av[threadIdx.x] = m[((size_t)b*NTOK + 2*i) * HDIM + threadIdx.x];
    __syncthreads();
    int j = threadIdx.x;
    const float* bm = m + ((size_t)b*NTOK + 2*j + 1) * HDIM;
    float s = 0.0f;
    #pragma unroll
    for (int d = 0; d < HDIM; d++) s += av[d] * bm[d];
    __shared__ float sv[128];
    __shared__ int   si[128];
    sv[j] = s; si[j] = j;
    __syncthreads();
    #pragma unroll
    for (int st = 64; st; st >>= 1) {
        if (threadIdx.x < st) {
            float o = sv[threadIdx.x + st]; int oi = si[threadIdx.x + st];
            if (o > sv[threadIdx.x] ||
                (o == sv[threadIdx.x] && oi < si[threadIdx.x])) {
                sv[threadIdx.x] = o; si[threadIdx.x] = oi;
            }
        }
        __syncthreads();
    }
    if (threadIdx.x == 0) { nmax[b*NA + i] = sv[0]; nidx[b*NA + i] = si[0]; }
}

// ---------------------------------------------------------------------------
// Stable descending argsort via ranks; build unm/src/dst/dcnt per batch.
// ---------------------------------------------------------------------------
__global__ __launch_bounds__(160)
void topo_kernel(const float* __restrict__ nmax, const int* __restrict__ nidx)
{
    int b = blockIdx.x;
    __shared__ float nm[NA];
    __shared__ int   rk[NA];
    int t = threadIdx.x;
    if (t < NA) nm[t] = nmax[b*NA + t];
    __syncthreads();
    if (t < NA) {
        float mi = nm[t];
        int r = 0;
        for (int j = 0; j < NA; j++) {
            float mj = nm[j];
            r += (mj > mi) || (mj == mi && j < t);
        }
        rk[t] = r;
        if (r < RR) {
            g_src[b][r] = t;
            g_dst[b][r] = nidx[b*NA + t];
        }
    }
    __syncthreads();
    if (t == 0) {
        int pos = 0;
        for (int i = 0; i < NA; i++)
            if (rk[i] >= RR) g_unm[b][pos++] = i;
    }
    if (t < NB) {
        int c = 0;
        for (int k = 0; k < RR; k++) c += (g_dst[b][k] == t);
        g_dcnt[b][t] = c;
    }
}

// ---------------------------------------------------------------------------
// ToME merge: out token t<113 = s[unm[t]]; else d[j] + mapped src, / size.
// ---------------------------------------------------------------------------
__global__ __launch_bounds__(256)
void merge_kernel(const float* __restrict__ xf, float* __restrict__ xm)
{
    int t = blockIdx.x % NOUT;
    int b = blockIdx.x / NOUT;
    __shared__ int ssrc[RR], sdst[RR];
    if (threadIdx.x < RR) {
        ssrc[threadIdx.x] = g_src[b][threadIdx.x];
        sdst[threadIdx.x] = g_dst[b][threadIdx.x];
    }
    __syncthreads();
    size_t brow = (size_t)b * NTOK;
    float4* out = (float4*)(xm + ((size_t)b * NOUT + t) * DD);
    int d = threadIdx.x;
    if (t < NUNM) {
        int u = g_unm[b][t];
        const float4* src = (const float4*)(xf + (brow + 2*u) * DD);
        out[d] = src[d];
    } else {
        int j = t - NUNM;
        const float4* dsrc = (const float4*)(xf + (brow + 2*j + 1) * DD);
        float4 v = dsrc[d];
        int cnt = g_dcnt[b][j];
        if (cnt) {
            #pragma unroll
            for (int k = 0; k < RR; k++) {
                if (sdst[k] == j) {
                    const float4* s2 =
                        (const float4*)(xf + (brow + 2*ssrc[k]) * DD);
                    float4 a = s2[d];
                    v.x += a.x; v.y += a.y; v.z += a.z; v.w += a.w;
                }
            }
            float inv = 1.0f / (float)(1 + cnt);
            v.x *= inv; v.y *= inv; v.z *= inv; v.w *= inv;
        }
        out[d] = v;
    }
}

// ---------------------------------------------------------------------------
// kernel_launch
// ---------------------------------------------------------------------------
extern "C" void kernel_launch(void* const* d_in, const int* in_sizes, int n_in,
                              void* d_out, int out_size)
{
    const float* q_x       = (const float*)d_in[0];
    const float* ln1_w     = (const float*)d_in[1];
    const float* ln1_b     = (const float*)d_in[2];
    const float* in_proj_w = (const float*)d_in[3];
    const float* in_proj_b = (const float*)d_in[4];
    const float* out_w     = (const float*)d_in[5];
    const float* out_b     = (const float*)d_in[6];
    const float* ln2_w     = (const float*)d_in[7];
    const float* ln2_b     = (const float*)d_in[8];
    const float* fc_w      = (const float*)d_in[9];
    const float* fc_b      = (const float*)d_in[10];
    const float* proj_w    = (const float*)d_in[11];
    const float* proj_b    = (const float*)d_in[12];
    float* outp = (float*)d_out;

    float *p_h, *p_ht, *p_qkv, *p_o, *p_xf, *p_m, *p_nmax, *p_xm, *p_h2, *p_t4;
    float *p_wavgT, *p_bavg, *p_win, *p_wout, *p_wfc, *p_wproj;
    int *p_nidx;
    cudaGetSymbolAddress((void**)&p_h,     g_h);
    cudaGetSymbolAddress((void**)&p_ht,    g_ht);
    cudaGetSymbolAddress((void**)&p_qkv,   g_qkv);
    cudaGetSymbolAddress((void**)&p_o,     g_o);
    cudaGetSymbolAddress((void**)&p_xf,    g_xf);
    cudaGetSymbolAddress((void**)&p_m,     g_m);
    cudaGetSymbolAddress((void**)&p_wavgT, g_wavgT);
    cudaGetSymbolAddress((void**)&p_bavg,  g_bavg);
    cudaGetSymbolAddress((void**)&p_nmax,  g_nmax);
    cudaGetSymbolAddress((void**)&p_nidx,  g_nidx);
    cudaGetSymbolAddress((void**)&p_xm,    g_xm);
    cudaGetSymbolAddress((void**)&p_h2,    g_h2);
    cudaGetSymbolAddress((void**)&p_t4,    g_t4);
    cudaGetSymbolAddress((void**)&p_win,   g_w_in);
    cudaGetSymbolAddress((void**)&p_wout,  g_w_out);
    cudaGetSymbolAddress((void**)&p_wfc,   g_w_fc);
    cudaGetSymbolAddress((void**)&p_wproj, g_w_proj);

    static const int ATT_SMEM = (NTOK*KST*2 + 8*PRST + 8*HDIM) * 4;
    cudaFuncSetAttribute(attn_kernel,
                         cudaFuncAttributeMaxDynamicSharedMemorySize, ATT_SMEM);
    cudaFuncSetAttribute(gemm_tf32<0>,
                         cudaFuncAttributeMaxDynamicSharedMemorySize, GEMM_SMEM);
    cudaFuncSetAttribute(gemm_tf32<1>,
                         cudaFuncAttributeMaxDynamicSharedMemorySize, GEMM_SMEM);
    cudaFuncSetAttribute(gemm_tf32<2>,
                         cudaFuncAttributeMaxDynamicSharedMemorySize, GEMM_SMEM);

    // 0a. round weights to tf32 copies
    roundw_kernel<<<(3*DD*DD/4 + 255)/256, 256>>>(
        (const float4*)in_proj_w, (float4*)p_win, 3*DD*DD/4);
    roundw_kernel<<<(DD*DD/4 + 255)/256, 256>>>(
        (const float4*)out_w, (float4*)p_wout, DD*DD/4);
    roundw_kernel<<<(4*DD*DD/4 + 255)/256, 256>>>(
        (const float4*)fc_w, (float4*)p_wfc, 4*DD*DD/4);
    roundw_kernel<<<(4*DD*DD/4 + 255)/256, 256>>>(
        (const float4*)proj_w, (float4*)p_wproj, 4*DD*DD/4);

    // 0b. head-averaged k weights (exact metric path)
    wavg_kernel<<<HDIM, 256>>>(in_proj_w, in_proj_b, p_wavgT, p_bavg);

    // 1. LN1 -> exact (metric) + rounded (GEMM A)
    ln_kernel<<<MROWS, 256>>>(q_x, ln1_w, ln1_b, p_h, p_ht);

    // 2. qkv = h @ in_proj_w^T + b
    gemm_tf32<0><<<dim3(3072/128, (MROWS+127)/128), 256, GEMM_SMEM>>>(
        p_ht, p_win, in_proj_b, nullptr, p_qkv, MROWS, 3072, 1024);

    // 3. metric (fp32 exact, tiled) + normalize
    metric_gemm_kernel<<<MROWS/32, 256>>>(p_h, p_wavgT, p_bavg, p_m);

    // 4. attention -> o (rounded)
    attn_kernel<<<BATCH*HEADS, 256, ATT_SMEM>>>(p_qkv, p_o);

    // 5. x = q_x + o @ out_w^T + out_b   (exact residual out)
    gemm_tf32<1><<<dim3(1024/128, (MROWS+127)/128), 256, GEMM_SMEM>>>(
        p_o, p_wout, out_b, q_x, p_xf, MROWS, 1024, 1024);

    // 6. node scores
    nodescore_kernel<<<dim3(NA, BATCH), 128>>>(p_m, p_nmax, p_nidx);

    // 7. stable ranks / merge bookkeeping
    topo_kernel<<<BATCH, 160>>>(p_nmax, p_nidx);

    // 8. merge tokens 257 -> 241
    merge_kernel<<<BATCH*NOUT, 256>>>(p_xf, p_xm);

    // 9. LN2 -> rounded only (feeds fc GEMM only)
    ln_kernel<<<MOUT, 256>>>(p_xm, ln2_w, ln2_b, nullptr, p_h2);

    // 10. t = gelu(h2 @ fc_w^T + fc_b)  (rounded out)
    gemm_tf32<2><<<dim3(4096/128, (MOUT+127)/128), 256, GEMM_SMEM>>>(
        p_h2, p_wfc, fc_b, nullptr, p_t4, MOUT, 4096, 1024);

    // 11. out = x + t @ proj_w^T + proj_b  (exact)
    gemm_tf32<1><<<dim3(1024/128, (MOUT+127)/128), 256, GEMM_SMEM>>>(
        p_t4, p_wproj, proj_b, p_xm, outp, MOUT, 1024, 4096);
}

// round 16
// speedup vs baseline: 1.0020x; 1.0020x over previous
#include <cuda_runtime.h>
#include <math.h>
#include <stdint.h>

// ---------------------------------------------------------------------------
// Problem constants
// ---------------------------------------------------------------------------
#define DD    1024
#define NTOK  257
#define BATCH 32
#define HEADS 16
#define HDIM  64
#define RR    16
#define NA    129        // even tokens (a side)
#define NB    128        // odd tokens  (b side)
#define NUNM  113        // NA - RR
#define NOUT  241        // NUNM + NB
#define MROWS (BATCH*NTOK)   // 8224
#define MOUT  (BATCH*NOUT)   // 7712

// ---------------------------------------------------------------------------
// Scratch (device globals -- no allocation allowed)
// ---------------------------------------------------------------------------
__device__ float g_h   [MROWS*DD];          // LN1 output (fp32 exact, metric path)
__device__ float g_ht  [MROWS*DD];          // LN1 output (tf32-rounded, GEMM A)
__device__ float g_qkv [MROWS*3*DD];        // qkv projections
__device__ float g_o   [MROWS*DD];          // attention output (tf32-rounded)
__device__ float g_xf  [MROWS*DD];          // x after attention residual (exact)
__device__ float g_m   [MROWS*HDIM];        // normalized metric (fp32 path)
__device__ float g_wavgT[DD*HDIM];          // head-averaged Wk, transposed
__device__ float g_bavg [HDIM];
__device__ float g_nmax[BATCH*NA];
__device__ int   g_nidx[BATCH*NA];
__device__ int   g_unm [BATCH][NUNM];
__device__ int   g_src [BATCH][RR];
__device__ int   g_dst [BATCH][RR];
__device__ int   g_dcnt[BATCH][NB];
__device__ float g_xm  [MOUT*DD];           // merged x (exact)
__device__ float g_h2  [MOUT*DD];           // LN2 output (tf32-rounded)
__device__ float g_t4  [MOUT*4*DD];         // fc+gelu output (tf32-rounded)
// tf32-rounded weight copies
__device__ float g_w_in  [3*DD*DD];
__device__ float g_w_out [DD*DD];
__device__ float g_w_fc  [4*DD*DD];
__device__ float g_w_proj[4*DD*DD];

// ---------------------------------------------------------------------------
// Helpers
// ---------------------------------------------------------------------------
__device__ __forceinline__ float gelu_exact(float x) {
    return 0.5f * x * (1.0f + erff(x * 0.70710678118654752440f));
}

__device__ __forceinline__ unsigned f2tf(float x) {
    unsigned u;
    asm("cvt.rna.tf32.f32 %0, %1;" : "=r"(u) : "f"(x));
    return u;
}
__device__ __forceinline__ float rtf(float x) {
    return __uint_as_float(f2tf(x));
}

__device__ __forceinline__ uint32_t smem_u32(const void* p) {
    uint32_t a;
    asm("{ .reg .u64 t; cvta.to.shared.u64 t, %1; cvt.u32.u64 %0, t; }"
        : "=r"(a) : "l"(p));
    return a;
}

__device__ __forceinline__ void cp16(uint32_t s, const void* g) {
    asm volatile("cp.async.cg.shared.global [%0], [%1], 16;"
                 :: "r"(s), "l"(g) : "memory");
}
#define CP_COMMIT() asm volatile("cp.async.commit_group;" ::: "memory")
#define CP_WAIT1()  asm volatile("cp.async.wait_group 1;" ::: "memory")
#define CP_WAIT0()  asm volatile("cp.async.wait_group 0;" ::: "memory")

__device__ __forceinline__ void mma_tf32(float c[4], const unsigned a[4],
                                         const unsigned b[2]) {
    asm volatile(
        "mma.sync.aligned.m16n8k8.row.col.f32.tf32.tf32.f32 "
        "{%0,%1,%2,%3}, {%4,%5,%6,%7}, {%8,%9}, {%0,%1,%2,%3};\n"
        : "+f"(c[0]), "+f"(c[1]), "+f"(c[2]), "+f"(c[3])
        : "r"(a[0]), "r"(a[1]), "r"(a[2]), "r"(a[3]),
          "r"(b[0]), "r"(b[1]));
}

// ---------------------------------------------------------------------------
// Round ALL weights to tf32 (rna) into scratch copies -- single fused launch.
// Segments (in float4 units): in_proj 786432 | out 262144 | fc 1048576 |
// proj 1048576; total 3145728.
// ---------------------------------------------------------------------------
#define N4_IN   (3*DD*DD/4)
#define N4_OUT  (DD*DD/4)
#define N4_FC   (4*DD*DD/4)
#define N4_PROJ (4*DD*DD/4)
#define N4_TOT  (N4_IN + N4_OUT + N4_FC + N4_PROJ)

__global__ __launch_bounds__(256)
void roundw_all_kernel(const float4* __restrict__ w_in,
                       const float4* __restrict__ w_out,
                       const float4* __restrict__ w_fc,
                       const float4* __restrict__ w_proj,
                       float4* __restrict__ d_in,
                       float4* __restrict__ d_out,
                       float4* __restrict__ d_fc,
                       float4* __restrict__ d_proj)
{
    int i = blockIdx.x * blockDim.x + threadIdx.x;
    const float4* s; float4* d; int off;
    if (i < N4_IN)                       { s = w_in;   d = d_in;   off = 0; }
    else if (i < N4_IN+N4_OUT)           { s = w_out;  d = d_out;  off = N4_IN; }
    else if (i < N4_IN+N4_OUT+N4_FC)     { s = w_fc;   d = d_fc;   off = N4_IN+N4_OUT; }
    else if (i < N4_TOT)                 { s = w_proj; d = d_proj; off = N4_IN+N4_OUT+N4_FC; }
    else return;
    int j = i - off;
    float4 v = s[j];
    v.x = rtf(v.x); v.y = rtf(v.y); v.z = rtf(v.z); v.w = rtf(v.w);
    d[j] = v;
}

// ---------------------------------------------------------------------------
// LayerNorm: one block per row of 1024, 256 threads (4 floats/thread).
// y: exact output (nullable). yt: tf32-rounded output (nullable).
// ---------------------------------------------------------------------------
__global__ __launch_bounds__(256)
void ln_kernel(const float* __restrict__ x, const float* __restrict__ w,
               const float* __restrict__ b, float* __restrict__ y,
               float* __restrict__ yt)
{
    int r = blockIdx.x;
    const float4* xr = (const float4*)(x + (size_t)r * DD);
    float4 v = xr[threadIdx.x];
    float s  = v.x + v.y + v.z + v.w;
    float s2 = v.x*v.x + v.y*v.y + v.z*v.z + v.w*v.w;
    #pragma unroll
    for (int off = 16; off; off >>= 1) {
        s  += __shfl_xor_sync(0xffffffffu, s,  off);
        s2 += __shfl_xor_sync(0xffffffffu, s2, off);
    }
    __shared__ float ws[8], ws2[8];
    int wid = threadIdx.x >> 5, lid = threadIdx.x & 31;
    if (lid == 0) { ws[wid] = s; ws2[wid] = s2; }
    __syncthreads();
    __shared__ float smu, srstd;
    if (threadIdx.x == 0) {
        float S = 0, S2 = 0;
        #pragma unroll
        for (int i = 0; i < 8; i++) { S += ws[i]; S2 += ws2[i]; }
        float mu  = S * (1.0f / DD);
        float var = S2 * (1.0f / DD) - mu * mu;
        smu = mu; srstd = rsqrtf(var + 1e-5f);
    }
    __syncthreads();
    float mu = smu, rstd = srstd;
    float4 wv = ((const float4*)w)[threadIdx.x];
    float4 bv = ((const float4*)b)[threadIdx.x];
    float4 o;
    o.x = (v.x - mu) * rstd * wv.x + bv.x;
    o.y = (v.y - mu) * rstd * wv.y + bv.y;
    o.z = (v.z - mu) * rstd * wv.z + bv.z;
    o.w = (v.w - mu) * rstd * wv.w + bv.w;
    if (y)
        ((float4*)(y + (size_t)r * DD))[threadIdx.x] = o;
    if (yt) {
        float4 t;
        t.x = rtf(o.x); t.y = rtf(o.y); t.z = rtf(o.z); t.w = rtf(o.w);
        ((float4*)(yt + (size_t)r * DD))[threadIdx.x] = t;
    }
}

// ---------------------------------------------------------------------------
// TF32 tensor-core GEMM (NT): C[m,n] = sum_k A[m,k]*W[n,k] + bias[n] (+epi)
// A and W must be tf32-pre-rounded. BM=BN=128, BK=32, 256 threads,
// warps 2x4 (warp tile 64x32). 2-stage cp.async pipeline, 2 CTAs/SM.
// (R14 measured-best configuration -- do not change the mainloop.)
// EPI 0: bias. EPI 1: +Cadd residual. EPI 2: gelu(acc+bias), tf32-rounded out.
// Requires N % 128 == 0, K % 64 == 0; M guarded.
// ---------------------------------------------------------------------------
#define SAS 36
#define BUFF 4608                 // floats per matrix per buffer (128*36)
#define BUFSTR 9216               // floats per buffer (A+B)
#define GEMM_SMEM (2*BUFSTR*4)    // 73728 bytes

template<int EPI>
__global__ __launch_bounds__(256, 2)
void gemm_tf32(const float* __restrict__ A, const float* __restrict__ W,
               const float* __restrict__ bias, const float* __restrict__ Cadd,
               float* __restrict__ C, int M, int N, int K)
{
    extern __shared__ float smem[];
    uint32_t sbase = smem_u32(smem);

    int tid = threadIdx.x;
    int bx = blockIdx.x, by = blockIdx.y;

    // gmem -> smem mapping: thread covers (row = rbase+32i, 16B chunk c4)
    int rbase = tid >> 3;          // 0..31
    int c4    = tid & 7;           // 0..7
    const float* Ag[4];
    const float* Wg[4];
    uint32_t sA[4], sB[4];
    #pragma unroll
    for (int i = 0; i < 4; i++) {
        int row = rbase + 32*i;
        int ar = by*128 + row; if (ar >= M) ar = M - 1;   // clamp, epi guards
        Ag[i] = A + (size_t)ar * K + c4*4;
        Wg[i] = W + (size_t)(bx*128 + row) * K + c4*4;
        sA[i] = sbase + (row*SAS + c4*4) * 4;
        sB[i] = sbase + ((BUFF + row*SAS) + c4*4) * 4;
    }

    int NC = K >> 5;

    // issue stage c into buffer c&1
    auto issue = [&](int c) {
        uint32_t off = (c & 1) ? (BUFSTR*4) : 0u;
        int ko = c * 32;
        #pragma unroll
        for (int i = 0; i < 4; i++) cp16(sA[i] + off, Ag[i] + ko);
        #pragma unroll
        for (int i = 0; i < 4; i++) cp16(sB[i] + off, Wg[i] + ko);
        CP_COMMIT();
    };

    issue(0);
    issue(1);

    float acc[4][4][4];
    #pragma unroll
    for (int mt = 0; mt < 4; mt++)
        #pragma unroll
        for (int nt = 0; nt < 4; nt++)
            #pragma unroll
            for (int q = 0; q < 4; q++) acc[mt][nt][q] = 0.0f;

    int w = tid >> 5, l = tid & 31;
    int wm = w >> 2, wn = w & 3;          // 2 x 4 warp grid
    int mrow = l >> 2;                    // 0..7
    int kc   = l & 3;                     // 0..3

    for (int c = 0; c < NC; c++) {
        if (c + 1 < NC) CP_WAIT1(); else CP_WAIT0();
        __syncthreads();

        const unsigned* As = (const unsigned*)smem + (c & 1)*BUFSTR;
        const unsigned* Bs = As + BUFF;

        #pragma unroll
        for (int kk = 0; kk < 4; kk++) {
            unsigned af[4][4], bf[4][2];
            #pragma unroll
            for (int mt = 0; mt < 4; mt++) {
                int base = (wm*64 + mt*16 + mrow) * SAS + kk*8 + kc;
                af[mt][0] = As[base];
                af[mt][1] = As[base + 8*SAS];
                af[mt][2] = As[base + 4];
                af[mt][3] = As[base + 8*SAS + 4];
            }
            #pragma unroll
            for (int nt = 0; nt < 4; nt++) {
                int base = (wn*32 + nt*8 + mrow) * SAS + kk*8 + kc;
                bf[nt][0] = Bs[base];
                bf[nt][1] = Bs[base + 4];
            }
            #pragma unroll
            for (int mt = 0; mt < 4; mt++)
                #pragma unroll
                for (int nt = 0; nt < 4; nt++)
                    mma_tf32(acc[mt][nt], af[mt], bf[nt]);
        }
        __syncthreads();
        if (c + 2 < NC) issue(c + 2);
    }

    // epilogue
    int gr0 = by*128 + wm*64;
    int gc0 = bx*128 + wn*32;
    #pragma unroll
    for (int mt = 0; mt < 4; mt++) {
        #pragma unroll
        for (int nt = 0; nt < 4; nt++) {
            int col = gc0 + nt*8 + kc*2;
            float2 bv = *(const float2*)(bias + col);
            #pragma unroll
            for (int half = 0; half < 2; half++) {
                int row = gr0 + mt*16 + mrow + half*8;
                if (row >= M) continue;
                float r0 = acc[mt][nt][half*2+0] + bv.x;
                float r1 = acc[mt][nt][half*2+1] + bv.y;
                if constexpr (EPI == 1) {
                    float2 cv = *(const float2*)(Cadd + (size_t)row*N + col);
                    r0 += cv.x; r1 += cv.y;
                }
                if constexpr (EPI == 2) {
                    r0 = rtf(gelu_exact(r0)); r1 = rtf(gelu_exact(r1));
                }
                float2 ov = {r0, r1};
                *(float2*)(C + (size_t)row*N + col) = ov;
            }
        }
    }
}

// ---------------------------------------------------------------------------
// Fused attention: one block per (b,h). K,V resident in smem (stride 65),
// per-warp softmax over 257 keys. Output tf32-rounded (feeds GEMM only).
// ---------------------------------------------------------------------------
#define KST 65
#define PRST 260
__global__ __launch_bounds__(256)
void attn_kernel(const float* __restrict__ qkv, float* __restrict__ o)
{
    extern __shared__ float sm[];
    float* Ks = sm;                       // 257*65
    float* Vs = sm + NTOK*KST;            // 257*65
    float* Pr = Vs + NTOK*KST;            // 8*260
    float* Qb = Pr + 8*PRST;              // 8*64

    int bh = blockIdx.x;
    int b = bh >> 4, hh = bh & 15;
    const float* base = qkv + (size_t)b * NTOK * (3*DD);

    for (int idx = threadIdx.x; idx < NTOK*HDIM; idx += blockDim.x) {
        int j = idx >> 6, d = idx & 63;
        Ks[j*KST + d] = base[(size_t)j*(3*DD) + DD   + hh*HDIM + d];
        Vs[j*KST + d] = base[(size_t)j*(3*DD) + 2*DD + hh*HDIM + d];
    }
    __syncthreads();

    int w = threadIdx.x >> 5, l = threadIdx.x & 31;
    float* pr = Pr + w * PRST;
    float* qb = Qb + w * HDIM;

    for (int n = w; n < NTOK; n += 8) {
        const float* qrow = base + (size_t)n*(3*DD) + hh*HDIM;
        qb[l]      = qrow[l];
        qb[l + 32] = qrow[l + 32];
        __syncwarp();
        float mx = -INFINITY;
        for (int j = l; j < NTOK; j += 32) {
            float s = 0.0f;
            #pragma unroll
            for (int d = 0; d < HDIM; d++) s += qb[d] * Ks[j*KST + d];
            s *= 0.125f;
            pr[j] = s;
            mx = fmaxf(mx, s);
        }
        #pragma unroll
        for (int off = 16; off; off >>= 1)
            mx = fmaxf(mx, __shfl_xor_sync(0xffffffffu, mx, off));
        float sum = 0.0f;
        for (int j = l; j < NTOK; j += 32) {
            float e = expf(pr[j] - mx);
            pr[j] = e;
            sum += e;
        }
        #pragma unroll
        for (int off = 16; off; off >>= 1)
            sum += __shfl_xor_sync(0xffffffffu, sum, off);
        float inv = 1.0f / sum;
        __syncwarp();
        float o0 = 0.0f, o1 = 0.0f;
        for (int j = 0; j < NTOK; j++) {
            float p = pr[j];
            o0 += p * Vs[j*KST + l];
            o1 += p * Vs[j*KST + l + 32];
        }
        float* orow = o + ((size_t)b*NTOK + n) * DD + hh*HDIM;
        orow[l]      = rtf(o0 * inv);
        orow[l + 32] = rtf(o1 * inv);
        __syncwarp();
    }
}

// ---------------------------------------------------------------------------
// Head-averaged k-weights (fp32 exact metric path)
// ---------------------------------------------------------------------------
__global__ __launch_bounds__(256)
void wavg_kernel(const float* __restrict__ Wqkv, const float* __restrict__ bqkv,
                 float* __restrict__ wavgT, float* __restrict__ bavg)
{
    int d = blockIdx.x;                   // 0..63
    for (int c = threadIdx.x; c < DD; c += 256) {
        float s = 0.0f;
        #pragma unroll
        for (int h = 0; h < HEADS; h++)
            s += Wqkv[(size_t)(DD + h*HDIM + d) * DD + c];
        wavgT[c*HDIM + d] = s * (1.0f / HEADS);
    }
    if (threadIdx.x == 0) {
        float s = 0.0f;
        #pragma unroll
        for (int h = 0; h < HEADS; h++) s += bqkv[DD + h*HDIM + d];
        bavg[d] = s * (1.0f / HEADS);
    }
}

// ---------------------------------------------------------------------------
// metric (fp32 exact), tiled: one block = 32 rows x 64 cols. wavgT is
// streamed through smem in 64-k chunks (32x less L2 traffic than the
// per-row version). h chunk stored transposed (stride 33) => conflict-free.
// Then per-row L2 normalization (8 threads/row, shfl reduce).
// ---------------------------------------------------------------------------
__global__ __launch_bounds__(256)
void metric_gemm_kernel(const float* __restrict__ h,
                        const float* __restrict__ wavgT,
                        const float* __restrict__ bavg,
                        float* __restrict__ m)
{
    __shared__ float hsm[64*33];          // [k][row], stride 33
    __shared__ float wsm[64*64];          // [k][d]
    int tid = threadIdx.x;
    int row = tid >> 3;                   // 0..31
    int cg  = tid & 7;                    // cols cg*8 .. cg*8+7
    int rbase = blockIdx.x * 32;

    float acc[8] = {0,0,0,0,0,0,0,0};

    for (int k0 = 0; k0 < DD; k0 += 64) {
        __syncthreads();
        // load h chunk transposed: thread covers row, k = cg*8..cg*8+7
        {
            const float4* s =
                (const float4*)(h + (size_t)(rbase + row)*DD + k0 + cg*8);
            float4 v0 = s[0], v1 = s[1];
            int kb = cg*8;
            hsm[(kb+0)*33 + row] = v0.x; hsm[(kb+1)*33 + row] = v0.y;
            hsm[(kb+2)*33 + row] = v0.z; hsm[(kb+3)*33 + row] = v0.w;
            hsm[(kb+4)*33 + row] = v1.x; hsm[(kb+5)*33 + row] = v1.y;
            hsm[(kb+6)*33 + row] = v1.z; hsm[(kb+7)*33 + row] = v1.w;
        }
        // load w chunk: 64 k x 64 d = 4096 floats = 4 float4 per thread
        #pragma unroll
        for (int i = 0; i < 4; i++) {
            int idx = tid + 256*i;
            int kk = idx >> 4, d4 = idx & 15;
            *(float4*)&wsm[kk*64 + d4*4] =
                *(const float4*)(wavgT + (size_t)(k0+kk)*HDIM + d4*4);
        }
        __syncthreads();

        #pragma unroll 8
        for (int k = 0; k < 64; k++) {
            float hv = hsm[k*33 + row];
            float4 w0 = *(const float4*)&wsm[k*64 + cg*8];
            float4 w1 = *(const float4*)&wsm[k*64 + cg*8 + 4];
            acc[0] += hv*w0.x; acc[1] += hv*w0.y;
            acc[2] += hv*w0.z; acc[3] += hv*w0.w;
            acc[4] += hv*w1.x; acc[5] += hv*w1.y;
            acc[6] += hv*w1.z; acc[7] += hv*w1.w;
        }
    }

    // bias
    float4 b0 = *(const float4*)(bavg + cg*8);
    float4 b1 = *(const float4*)(bavg + cg*8 + 4);
    acc[0]+=b0.x; acc[1]+=b0.y; acc[2]+=b0.z; acc[3]+=b0.w;
    acc[4]+=b1.x; acc[5]+=b1.y; acc[6]+=b1.z; acc[7]+=b1.w;

    // row L2 norm across 8 threads (8-lane shfl groups)
    float sq = 0.0f;
    #pragma unroll
    for (int j = 0; j < 8; j++) sq += acc[j]*acc[j];
    sq += __shfl_xor_sync(0xffffffffu, sq, 1);
    sq += __shfl_xor_sync(0xffffffffu, sq, 2);
    sq += __shfl_xor_sync(0xffffffffu, sq, 4);
    float rn = rsqrtf(sq);

    float* out = m + (size_t)(rbase + row)*HDIM + cg*8;
    float4 o0 = {acc[0]*rn, acc[1]*rn, acc[2]*rn, acc[3]*rn};
    float4 o1 = {acc[4]*rn, acc[5]*rn, acc[6]*rn, acc[7]*rn};
    *(float4*)out = o0;
    *(float4*)(out + 4) = o1;
}

// ---------------------------------------------------------------------------
// node scores: block (i,b) computes max_j dot(a_i, bm_j) and argmax (first
// max wins). Row i==0 forced to -inf.
// ---------------------------------------------------------------------------
__global__ __launch_bounds__(128)
void nodescore_kernel(const float* __restrict__ m,
                      float* __restrict__ nmax, int* __restrict__ nidx)
{
    int i = blockIdx.x, b = blockIdx.y;
    if (i == 0) {
        if (threadIdx.x == 0) { nmax[b*NA] = -INFINITY; nidx[b*NA] = 0; }
        return;
    }
    __shared__ float av[HDIM];
    if (threadIdx.x < HDIM)
        av[threadIdx.x] = m[((size_t)b*NTOK + 2*i) * HDIM + threadIdx.x];
    __syncthreads();
    int j = threadIdx.x;
    const float* bm = m + ((size_t)b*NTOK + 2*j + 1) * HDIM;
    float s = 0.0f;
    #pragma unroll
    for (int d = 0; d < HDIM; d++) s += av[d] * bm[d];
    __shared__ float sv[128];
    __shared__ int   si[128];
    sv[j] = s; si[j] = j;
    __syncthreads();
    #pragma unroll
    for (int st = 64; st; st >>= 1) {
        if (threadIdx.x < st) {
            float o = sv[threadIdx.x + st]; int oi = si[threadIdx.x + st];
            if (o > sv[threadIdx.x] ||
                (o == sv[threadIdx.x] && oi < si[threadIdx.x])) {
                sv[threadIdx.x] = o; si[threadIdx.x] = oi;
            }
        }
        __syncthreads();
    }
    if (threadIdx.x == 0) { nmax[b*NA + i] = sv[0]; nidx[b*NA + i] = si[0]; }
}

// ---------------------------------------------------------------------------
// Stable descending argsort via ranks; build unm/src/dst/dcnt per batch.
// ---------------------------------------------------------------------------
__global__ __launch_bounds__(160)
void topo_kernel(const float* __restrict__ nmax, const int* __restrict__ nidx)
{
    int b = blockIdx.x;
    __shared__ float nm[NA];
    __shared__ int   rk[NA];
    int t = threadIdx.x;
    if (t < NA) nm[t] = nmax[b*NA + t];
    __syncthreads();
    if (t < NA) {
        float mi = nm[t];
        int r = 0;
        for (int j = 0; j < NA; j++) {
            float mj = nm[j];
            r += (mj > mi) || (mj == mi && j < t);
        }
        rk[t] = r;
        if (r < RR) {
            g_src[b][r] = t;
            g_dst[b][r] = nidx[b*NA + t];
        }
    }
    __syncthreads();
    if (t == 0) {
        int pos = 0;
        for (int i = 0; i < NA; i++)
            if (rk[i] >= RR) g_unm[b][pos++] = i;
    }
    if (t < NB) {
        int c = 0;
        for (int k = 0; k < RR; k++) c += (g_dst[b][k] == t);
        g_dcnt[b][t] = c;
    }
}

// ---------------------------------------------------------------------------
// ToME merge: out token t<113 = s[unm[t]]; else d[j] + mapped src, / size.
// ---------------------------------------------------------------------------
__global__ __launch_bounds__(256)
void merge_kernel(const float* __restrict__ xf, float* __restrict__ xm)
{
    int t = blockIdx.x % NOUT;
    int b = blockIdx.x / NOUT;
    __shared__ int ssrc[RR], sdst[RR];
    if (threadIdx.x < RR) {
        ssrc[threadIdx.x] = g_src[b][threadIdx.x];
        sdst[threadIdx.x] = g_dst[b][threadIdx.x];
    }
    __syncthreads();
    size_t brow = (size_t)b * NTOK;
    float4* out = (float4*)(xm + ((size_t)b * NOUT + t) * DD);
    int d = threadIdx.x;
    if (t < NUNM) {
        int u = g_unm[b][t];
        const float4* src = (const float4*)(xf + (brow + 2*u) * DD);
        out[d] = src[d];
    } else {
        int j = t - NUNM;
        const float4* dsrc = (const float4*)(xf + (brow + 2*j + 1) * DD);
        float4 v = dsrc[d];
        int cnt = g_dcnt[b][j];
        if (cnt) {
            #pragma unroll
            for (int k = 0; k < RR; k++) {
                if (sdst[k] == j) {
                    const float4* s2 =
                        (const float4*)(xf + (brow + 2*ssrc[k]) * DD);
                    float4 a = s2[d];
                    v.x += a.x; v.y += a.y; v.z += a.z; v.w += a.w;
                }
            }
            float inv = 1.0f / (float)(1 + cnt);
            v.x *= inv; v.y *= inv; v.z *= inv; v.w *= inv;
        }
        out[d] = v;
    }
}

// ---------------------------------------------------------------------------
// kernel_launch
// ---------------------------------------------------------------------------
extern "C" void kernel_launch(void* const* d_in, const int* in_sizes, int n_in,
                              void* d_out, int out_size)
{
    const float* q_x       = (const float*)d_in[0];
    const float* ln1_w     = (const float*)d_in[1];
    const float* ln1_b     = (const float*)d_in[2];
    const float* in_proj_w = (const float*)d_in[3];
    const float* in_proj_b = (const float*)d_in[4];
    const float* out_w     = (const float*)d_in[5];
    const float* out_b     = (const float*)d_in[6];
    const float* ln2_w     = (const float*)d_in[7];
    const float* ln2_b     = (const float*)d_in[8];
    const float* fc_w      = (const float*)d_in[9];
    const float* fc_b      = (const float*)d_in[10];
    const float* proj_w    = (const float*)d_in[11];
    const float* proj_b    = (const float*)d_in[12];
    float* outp = (float*)d_out;

    float *p_h, *p_ht, *p_qkv, *p_o, *p_xf, *p_m, *p_nmax, *p_xm, *p_h2, *p_t4;
    float *p_wavgT, *p_bavg, *p_win, *p_wout, *p_wfc, *p_wproj;
    int *p_nidx;
    cudaGetSymbolAddress((void**)&p_h,     g_h);
    cudaGetSymbolAddress((void**)&p_ht,    g_ht);
    cudaGetSymbolAddress((void**)&p_qkv,   g_qkv);
    cudaGetSymbolAddress((void**)&p_o,     g_o);
    cudaGetSymbolAddress((void**)&p_xf,    g_xf);
    cudaGetSymbolAddress((void**)&p_m,     g_m);
    cudaGetSymbolAddress((void**)&p_wavgT, g_wavgT);
    cudaGetSymbolAddress((void**)&p_bavg,  g_bavg);
    cudaGetSymbolAddress((void**)&p_nmax,  g_nmax);
    cudaGetSymbolAddress((void**)&p_nidx,  g_nidx);
    cudaGetSymbolAddress((void**)&p_xm,    g_xm);
    cudaGetSymbolAddress((void**)&p_h2,    g_h2);
    cudaGetSymbolAddress((void**)&p_t4,    g_t4);
    cudaGetSymbolAddress((void**)&p_win,   g_w_in);
    cudaGetSymbolAddress((void**)&p_wout,  g_w_out);
    cudaGetSymbolAddress((void**)&p_wfc,   g_w_fc);
    cudaGetSymbolAddress((void**)&p_wproj, g_w_proj);

    static const int ATT_SMEM = (NTOK*KST*2 + 8*PRST + 8*HDIM) * 4;
    cudaFuncSetAttribute(attn_kernel,
                         cudaFuncAttributeMaxDynamicSharedMemorySize, ATT_SMEM);
    cudaFuncSetAttribute(gemm_tf32<0>,
                         cudaFuncAttributeMaxDynamicSharedMemorySize, GEMM_SMEM);
    cudaFuncSetAttribute(gemm_tf32<1>,
                         cudaFuncAttributeMaxDynamicSharedMemorySize, GEMM_SMEM);
    cudaFuncSetAttribute(gemm_tf32<2>,
                         cudaFuncAttributeMaxDynamicSharedMemorySize, GEMM_SMEM);

    // 0a. round all weights to tf32 copies (single fused launch)
    roundw_all_kernel<<<(N4_TOT + 255)/256, 256>>>(
        (const float4*)in_proj_w, (const float4*)out_w,
        (const float4*)fc_w, (const float4*)proj_w,
        (float4*)p_win, (float4*)p_wout, (float4*)p_wfc, (float4*)p_wproj);

    // 0b. head-averaged k weights (exact metric path)
    wavg_kernel<<<HDIM, 256>>>(in_proj_w, in_proj_b, p_wavgT, p_bavg);

    // 1. LN1 -> exact (metric) + rounded (GEMM A)
    ln_kernel<<<MROWS, 256>>>(q_x, ln1_w, ln1_b, p_h, p_ht);

    // 2. qkv = h @ in_proj_w^T + b
    gemm_tf32<0><<<dim3(3072/128, (MROWS+127)/128), 256, GEMM_SMEM>>>(
        p_ht, p_win, in_proj_b, nullptr, p_qkv, MROWS, 3072, 1024);

    // 3. metric (fp32 exact, tiled) + normalize
    metric_gemm_kernel<<<MROWS/32, 256>>>(p_h, p_wavgT, p_bavg, p_m);

    // 4. attention -> o (rounded)
    attn_kernel<<<BATCH*HEADS, 256, ATT_SMEM>>>(p_qkv, p_o);

    // 5. x = q_x + o @ out_w^T + out_b   (exact residual out)
    gemm_tf32<1><<<dim3(1024/128, (MROWS+127)/128), 256, GEMM_SMEM>>>(
        p_o, p_wout, out_b, q_x, p_xf, MROWS, 1024, 1024);

    // 6. node scores
    nodescore_kernel<<<dim3(NA, BATCH), 128>>>(p_m, p_nmax, p_nidx);

    // 7. stable ranks / merge bookkeeping
    topo_kernel<<<BATCH, 160>>>(p_nmax, p_nidx);

    // 8. merge tokens 257 -> 241
    merge_kernel<<<BATCH*NOUT, 256>>>(p_xf, p_xm);

    // 9. LN2 -> rounded only (feeds fc GEMM only)
    ln_kernel<<<MOUT, 256>>>(p_xm, ln2_w, ln2_b, nullptr, p_h2);

    // 10. t = gelu(h2 @ fc_w^T + fc_b)  (rounded out)
    gemm_tf32<2><<<dim3(4096/128, (MOUT+127)/128), 256, GEMM_SMEM>>>(
        p_h2, p_wfc, fc_b, nullptr, p_t4, MOUT, 4096, 1024);

    // 11. out = x + t @ proj_w^T + proj_b  (exact)
    gemm_tf32<1><<<dim3(1024/128, (MOUT+127)/128), 256, GEMM_SMEM>>>(
        p_t4, p_wproj, proj_b, p_xm, outp, MOUT, 1024, 4096);
}